// round 11
// baseline (speedup 1.0000x reference)
#include <cuda_runtime.h>

// Shape fixed by setup_inputs: x [8, 8192, 512] fp32, weight [512] fp32.
#define BB 8
#define TT 8192
#define CC 512
#define EPSF 1e-5f

#define THREADS 256              // 8 warps; 4 blocks/SM -> 512 blocks, 1 wave
#define FPB 32                   // frames per tile (1 per lane in scans)
#define BPB (TT / FPB)           // 256 tiles per batch
#define NTILES (BB * TT / FPB)   // 2048 tiles
#define NBLK 512                 // blocks; 4 tiles each
#define PIPE 4                   // pipeline depth (tiles per block)
#define FPW (FPB / 8)            // 4 frames per warp per tile

// Double-buffered published aggregates: low 32b = value, high 32b = flag.
__device__ unsigned long long g_pubS1[2][NTILES];
__device__ unsigned long long g_pubD[2][NTILES];
__device__ int g_parity;
__device__ unsigned int g_done;

__device__ __forceinline__ void publish(unsigned long long* slot, float v) {
    *(volatile unsigned long long*)slot =
        (1ull << 32) | (unsigned long long)__float_as_uint(v);
}

// Warp-collective: sum predecessor aggregates [0, kb), kb <= 255.
// Issue all 8 candidate loads first (one L2 round-trip), spin on stragglers.
__device__ __forceinline__ float lookback(unsigned long long* base, int kb, int lane) {
    unsigned long long u[8];
#pragma unroll
    for (int k = 0; k < 8; k++) {
        const int idx = lane + k * 32;
        u[k] = (idx < kb) ? *(volatile unsigned long long*)&base[idx] : (1ull << 32);
    }
    float v = 0.f;
#pragma unroll
    for (int k = 0; k < 8; k++) {
        const int idx = lane + k * 32;
        if (idx < kb) {
            while (!(u[k] >> 32)) u[k] = *(volatile unsigned long long*)&base[idx];
            v += __uint_as_float((unsigned)u[k]);
        }
    }
#pragma unroll
    for (int o = 16; o > 0; o >>= 1) v += __shfl_xor_sync(0xffffffffu, v, o);
    return v;
}

__device__ __forceinline__ float warpscan(float v, int lane) {
#pragma unroll
    for (int o = 1; o < 32; o <<= 1) {
        float t = __shfl_up_sync(0xffffffffu, v, o);
        if (lane >= o) v += t;
    }
    return v;
}

// Per-frame reductions for one 32-frame tile (2-frame MLP batching).
__device__ __forceinline__ void reduce_tile(const float* __restrict__ x,
                                            size_t frame0, float* sS1, float* sQ,
                                            int wid, int lane) {
#pragma unroll
    for (int j = 0; j < FPW; j += 2) {
        const int f = wid * FPW + j;
        const float4* p0 = reinterpret_cast<const float4*>(x + (frame0 + f) * CC);
        const float4* p1 = reinterpret_cast<const float4*>(x + (frame0 + f + 1) * CC);
        float4 a[4], c[4];
#pragma unroll
        for (int k = 0; k < 4; k++) a[k] = p0[lane + k * 32];
#pragma unroll
        for (int k = 0; k < 4; k++) c[k] = p1[lane + k * 32];

        float s0 = 0.f, q0 = 0.f, s1 = 0.f, q1 = 0.f;
#pragma unroll
        for (int k = 0; k < 4; k++) {
            s0 += (a[k].x + a[k].y) + (a[k].z + a[k].w);
            q0 += a[k].x * a[k].x + a[k].y * a[k].y + a[k].z * a[k].z + a[k].w * a[k].w;
            s1 += (c[k].x + c[k].y) + (c[k].z + c[k].w);
            q1 += c[k].x * c[k].x + c[k].y * c[k].y + c[k].z * c[k].z + c[k].w * c[k].w;
        }
#pragma unroll
        for (int o = 16; o > 0; o >>= 1) {
            s0 += __shfl_xor_sync(0xffffffffu, s0, o);
            q0 += __shfl_xor_sync(0xffffffffu, q0, o);
            s1 += __shfl_xor_sync(0xffffffffu, s1, o);
            q1 += __shfl_xor_sync(0xffffffffu, q1, o);
        }
        if (lane == 0) {
            sS1[f] = s0; sQ[f] = q0;
            sS1[f + 1] = s1; sQ[f + 1] = q1;
        }
    }
}

// Warp 0: lookbacks + per-frame mean/inv for one tile (1 frame per lane).
// Publishes D before its own D-lookback (no cross-block chaining).
__device__ __forceinline__ void stats(int tile, int p, int lane,
                                      const float* sS1, const float* sQ,
                                      float* sMean, float* sInv) {
    const int kb = tile % BPB;
    const int batch = tile / BPB;

    const float a = sS1[lane];
    const float q = sQ[lane];

    const float incl = warpscan(a, lane);
    const float exclB = lookback(&g_pubS1[p][batch * BPB], kb, lane);

    const int t = kb * FPB + lane;
    const float cnt = (float)(t + 1) * (float)CC;
    const float m = (exclB + incl) / cnt;

    const float D = q - 2.f * m * a + (float)CC * m * m;
    const float dincl = warpscan(D, lane);
    if (lane == 31) publish(&g_pubD[p][tile], dincl);
    const float dexclB = lookback(&g_pubD[p][batch * BPB], kb, lane);

    sMean[lane] = m;
    sInv[lane] = rsqrtf((dexclB + dincl) / cnt + EPSF);
}

// Normalize one tile (evict-first reads, streaming stores).
__device__ __forceinline__ void norm_tile(const float* __restrict__ x,
                                          const float* __restrict__ w,
                                          float* __restrict__ out, size_t frame0,
                                          const float* sMean, const float* sInv,
                                          int wid, int lane) {
#pragma unroll
    for (int j = 0; j < FPW; j += 2) {
        const int f = wid * FPW + j;
        const float m0 = sMean[f], iv0 = sInv[f];
        const float m1 = sMean[f + 1], iv1 = sInv[f + 1];
        const float4* p0 = reinterpret_cast<const float4*>(x + (frame0 + f) * CC);
        const float4* p1 = reinterpret_cast<const float4*>(x + (frame0 + f + 1) * CC);
        const float4* w4 = reinterpret_cast<const float4*>(w);
        float4* o0 = reinterpret_cast<float4*>(out + (frame0 + f) * CC);
        float4* o1 = reinterpret_cast<float4*>(out + (frame0 + f + 1) * CC);

        float4 a[4], c[4];
#pragma unroll
        for (int k = 0; k < 4; k++) a[k] = __ldcs(p0 + lane + k * 32);
#pragma unroll
        for (int k = 0; k < 4; k++) c[k] = __ldcs(p1 + lane + k * 32);

#pragma unroll
        for (int k = 0; k < 4; k++) {
            float4 wv = w4[lane + k * 32];  // L1-hot
            float4 r0, r1;
            r0.x = (a[k].x - m0) * iv0 * wv.x;
            r0.y = (a[k].y - m0) * iv0 * wv.y;
            r0.z = (a[k].z - m0) * iv0 * wv.z;
            r0.w = (a[k].w - m0) * iv0 * wv.w;
            r1.x = (c[k].x - m1) * iv1 * wv.x;
            r1.y = (c[k].y - m1) * iv1 * wv.y;
            r1.z = (c[k].z - m1) * iv1 * wv.z;
            r1.w = (c[k].w - m1) * iv1 * wv.w;
            __stcs(&o0[lane + k * 32], r0);
            __stcs(&o1[lane + k * 32], r1);
        }
    }
}

__global__ void __launch_bounds__(THREADS, 4)
fused(const float* __restrict__ x, const float* __restrict__ w,
      float* __restrict__ out) {
    __shared__ float sS1[PIPE][FPB], sQ[PIPE][FPB];
    __shared__ float sMean[PIPE][FPB], sInv[PIPE][FPB];

    const int p = *(volatile int*)&g_parity;
    const int wid = threadIdx.x >> 5;
    const int lane = threadIdx.x & 31;

    // Tiles owned by this block: blockIdx + k*NBLK, k = 0..PIPE-1.
    // Within any batch (256 consecutive tiles) all tiles share the same k,
    // so a tile's predecessors belong to lower blockIdx at the same stage.
    int tiles[PIPE];
#pragma unroll
    for (int k = 0; k < PIPE; k++) tiles[k] = blockIdx.x + k * NBLK;

    // Clear the other parity's slots for the NEXT launch.
    if (threadIdx.x < PIPE) {
        const int t = blockIdx.x + threadIdx.x * NBLK;
        *(volatile unsigned long long*)&g_pubS1[1 - p][t] = 0ull;
        *(volatile unsigned long long*)&g_pubD[1 - p][t] = 0ull;
    }

    // -------- stage 1: reduce + publish S1 for all PIPE tiles --------------
#pragma unroll
    for (int k = 0; k < PIPE; k++) {
        reduce_tile(x, (size_t)tiles[k] * FPB, sS1[k], sQ[k], wid, lane);
        __syncthreads();
        if (wid == 0) {
            const float incl = warpscan(sS1[k][lane], lane);
            if (lane == 31) publish(&g_pubS1[p][tiles[k]], incl);
        }
    }

    // -------- stage 2: join tile 0 (predecessors published ~3 phases ago) --
    if (wid == 0) stats(tiles[0], p, lane, sS1[0], sQ[0], sMean[0], sInv[0]);
    __syncthreads();

    // -------- stage 3: norm tile k while warp 0 resolves join k+1 ----------
#pragma unroll
    for (int k = 0; k < PIPE; k++) {
        if (wid == 0 && k + 1 < PIPE)
            stats(tiles[k + 1], p, lane, sS1[k + 1], sQ[k + 1],
                  sMean[k + 1], sInv[k + 1]);
        norm_tile(x, w, out, (size_t)tiles[k] * FPB, sMean[k], sInv[k], wid, lane);
        if (k + 1 < PIPE) __syncthreads();   // protect sMean/sInv[k+1]
    }

    // -------- epilogue: last block flips parity ----------------------------
    __syncthreads();
    if (threadIdx.x == 0) {
        __threadfence();
        unsigned int n = atomicAdd(&g_done, 1u);
        if (n == NBLK - 1) {
            g_done = 0;
            g_parity = p ^ 1;
        }
    }
}

extern "C" void kernel_launch(void* const* d_in, const int* in_sizes, int n_in,
                              void* d_out, int out_size) {
    const float* x = (const float*)d_in[0];
    const float* w = (const float*)d_in[1];
    float* out = (float*)d_out;
    fused<<<NBLK, THREADS>>>(x, w, out);
}

// round 13
// speedup vs baseline: 1.1807x; 1.1807x over previous
#include <cuda_runtime.h>

// Shape fixed by setup_inputs: x [8, 8192, 512] fp32, weight [512] fp32.
#define BB 8
#define TT 8192
#define CC 512
#define EPSF 1e-5f

#define THREADS 256              // 8 warps; 4 blocks/SM -> 512 blocks, 1 wave
#define FPB 64                   // frames per tile
#define BPB (TT / FPB)           // 128 tiles per batch
#define NTILES (BB * TT / FPB)   // 1024 tiles
#define NBLK (NTILES / 2)        // 512 blocks, 2 tiles each
#define FPW (FPB / 8)            // 8 frames per warp per tile

// Double-buffered published aggregates: low 32b = value, high 32b = flag.
__device__ unsigned long long g_pubS1[2][NTILES];
__device__ unsigned long long g_pubD[2][NTILES];
__device__ int g_parity;
__device__ unsigned int g_done;

__device__ __forceinline__ void publish(unsigned long long* slot, float v) {
    *(volatile unsigned long long*)slot =
        (1ull << 32) | (unsigned long long)__float_as_uint(v);
}

// 32-byte evict-last load (sm_103a requires v8.b32 for L2::evict_last).
// Keeps x lines L2-resident for the phase-3 re-read.
struct F8 { float v[8]; };
__device__ __forceinline__ F8 ldg_keep8(const float* p) {
    unsigned r0, r1, r2, r3, r4, r5, r6, r7;
    asm volatile(
        "ld.global.L2::evict_last.v8.b32 {%0,%1,%2,%3,%4,%5,%6,%7}, [%8];"
        : "=r"(r0), "=r"(r1), "=r"(r2), "=r"(r3),
          "=r"(r4), "=r"(r5), "=r"(r6), "=r"(r7)
        : "l"(p));
    F8 f;
    f.v[0] = __uint_as_float(r0); f.v[1] = __uint_as_float(r1);
    f.v[2] = __uint_as_float(r2); f.v[3] = __uint_as_float(r3);
    f.v[4] = __uint_as_float(r4); f.v[5] = __uint_as_float(r5);
    f.v[6] = __uint_as_float(r6); f.v[7] = __uint_as_float(r7);
    return f;
}

// Warp-collective: sum predecessor aggregates [0, kb), kb <= 127 (4 slots/lane).
__device__ __forceinline__ float lookback(unsigned long long* base, int kb, int lane) {
    float v = 0.f;
#pragma unroll
    for (int k = 0; k < 4; k++) {
        const int idx = lane + k * 32;
        if (idx < kb) {
            unsigned long long u;
            do {
                u = *(volatile unsigned long long*)&base[idx];
            } while (!(u >> 32));
            v += __uint_as_float((unsigned)u);
        }
    }
#pragma unroll
    for (int o = 16; o > 0; o >>= 1) v += __shfl_xor_sync(0xffffffffu, v, o);
    return v;
}

__device__ __forceinline__ float warpscan(float v, int lane) {
#pragma unroll
    for (int o = 1; o < 32; o <<= 1) {
        float t = __shfl_up_sync(0xffffffffu, v, o);
        if (lane >= o) v += t;
    }
    return v;
}

// Phase 1: per-frame reductions (2 frames per iteration, 32B evict-last loads).
// Lane covers 8-float chunks {lane, lane+32} of each 512-float frame.
__device__ __forceinline__ void reduce_tile(const float* __restrict__ x,
                                            size_t frame0, float* sS1, float* sQ,
                                            int wid, int lane) {
#pragma unroll
    for (int j = 0; j < FPW; j += 2) {
        const int f = wid * FPW + j;
        const float* p0 = x + (frame0 + f) * CC;
        const float* p1 = x + (frame0 + f + 1) * CC;
        F8 a0 = ldg_keep8(p0 + lane * 8);
        F8 a1 = ldg_keep8(p0 + (lane + 32) * 8);
        F8 c0 = ldg_keep8(p1 + lane * 8);
        F8 c1 = ldg_keep8(p1 + (lane + 32) * 8);

        float s0 = 0.f, q0 = 0.f, s1 = 0.f, q1 = 0.f;
#pragma unroll
        for (int k = 0; k < 8; k++) {
            s0 += a0.v[k] + a1.v[k];
            q0 += a0.v[k] * a0.v[k] + a1.v[k] * a1.v[k];
            s1 += c0.v[k] + c1.v[k];
            q1 += c0.v[k] * c0.v[k] + c1.v[k] * c1.v[k];
        }
#pragma unroll
        for (int o = 16; o > 0; o >>= 1) {
            s0 += __shfl_xor_sync(0xffffffffu, s0, o);
            q0 += __shfl_xor_sync(0xffffffffu, q0, o);
            s1 += __shfl_xor_sync(0xffffffffu, s1, o);
            q1 += __shfl_xor_sync(0xffffffffu, q1, o);
        }
        if (lane == 0) {
            sS1[f] = s0; sQ[f] = q0;
            sS1[f + 1] = s1; sQ[f + 1] = q1;
        }
    }
}

// Warp 0: publish this tile's S1 block-aggregate (2 frames/lane).
__device__ __forceinline__ void scan_publish(int tile, int p, const float* sS1,
                                             int lane) {
    const float a0 = sS1[2 * lane];
    const float a1 = sS1[2 * lane + 1];
    const float incl = warpscan(a0 + a1, lane);
    if (lane == 31) publish(&g_pubS1[p][tile], incl);
}

// Warp 0: lookbacks + per-frame mean/inv for one tile.
__device__ __forceinline__ void stats(int tile, int p, int lane,
                                      const float* sS1, const float* sQ,
                                      float* sMean, float* sInv) {
    const int kb = tile % BPB;
    const int batch = tile / BPB;
    unsigned long long* baseS = &g_pubS1[p][batch * BPB];
    unsigned long long* baseD = &g_pubD[p][batch * BPB];

    const float a0 = sS1[2 * lane];
    const float a1 = sS1[2 * lane + 1];
    const float q0 = sQ[2 * lane];
    const float q1 = sQ[2 * lane + 1];

    const float pairsum = a0 + a1;
    const float incl = warpscan(pairsum, lane);
    const float exclL = incl - pairsum;

    const float exclB = lookback(baseS, kb, lane);

    const int t0 = kb * FPB + 2 * lane;
    const float c0 = (float)(t0 + 1) * (float)CC;
    const float c1 = (float)(t0 + 2) * (float)CC;
    const float m0 = (exclB + exclL + a0) / c0;
    const float m1 = (exclB + exclL + a0 + a1) / c1;

    const float D0 = q0 - 2.f * m0 * a0 + (float)CC * m0 * m0;
    const float D1 = q1 - 2.f * m1 * a1 + (float)CC * m1 * m1;
    const float dpair = D0 + D1;
    const float dincl = warpscan(dpair, lane);
    const float dexclL = dincl - dpair;
    if (lane == 31) publish(&g_pubD[p][tile], dincl);

    const float dexclB = lookback(baseD, kb, lane);

    const float v0 = (dexclB + dexclL + D0) / c0;
    const float v1 = (dexclB + dexclL + D0 + D1) / c1;
    sMean[2 * lane] = m0;
    sMean[2 * lane + 1] = m1;
    sInv[2 * lane] = rsqrtf(v0 + EPSF);
    sInv[2 * lane + 1] = rsqrtf(v1 + EPSF);
}

// Phase 3: normalize one tile (evict-first re-reads, streaming stores).
__device__ __forceinline__ void norm_tile(const float* __restrict__ x,
                                          const float* __restrict__ w,
                                          float* __restrict__ out, size_t frame0,
                                          const float* sMean, const float* sInv,
                                          int wid, int lane) {
#pragma unroll
    for (int j = 0; j < FPW; j += 2) {
        const int f = wid * FPW + j;
        const float m0 = sMean[f], iv0 = sInv[f];
        const float m1 = sMean[f + 1], iv1 = sInv[f + 1];
        const float4* p0 = reinterpret_cast<const float4*>(x + (frame0 + f) * CC);
        const float4* p1 = reinterpret_cast<const float4*>(x + (frame0 + f + 1) * CC);
        const float4* w4 = reinterpret_cast<const float4*>(w);
        float4* o0 = reinterpret_cast<float4*>(out + (frame0 + f) * CC);
        float4* o1 = reinterpret_cast<float4*>(out + (frame0 + f + 1) * CC);

        float4 a[4], c[4];
#pragma unroll
        for (int k = 0; k < 4; k++) a[k] = __ldcs(p0 + lane + k * 32);
#pragma unroll
        for (int k = 0; k < 4; k++) c[k] = __ldcs(p1 + lane + k * 32);

#pragma unroll
        for (int k = 0; k < 4; k++) {
            float4 wv = w4[lane + k * 32];  // L1-hot
            float4 r0, r1;
            r0.x = (a[k].x - m0) * iv0 * wv.x;
            r0.y = (a[k].y - m0) * iv0 * wv.y;
            r0.z = (a[k].z - m0) * iv0 * wv.z;
            r0.w = (a[k].w - m0) * iv0 * wv.w;
            r1.x = (c[k].x - m1) * iv1 * wv.x;
            r1.y = (c[k].y - m1) * iv1 * wv.y;
            r1.z = (c[k].z - m1) * iv1 * wv.z;
            r1.w = (c[k].w - m1) * iv1 * wv.w;
            __stcs(&o0[lane + k * 32], r0);
            __stcs(&o1[lane + k * 32], r1);
        }
    }
}

__global__ void __launch_bounds__(THREADS, 4)
fused(const float* __restrict__ x, const float* __restrict__ w,
      float* __restrict__ out) {
    __shared__ float sS1[2][FPB], sQ[2][FPB], sMean[2][FPB], sInv[2][FPB];

    const int p = *(volatile int*)&g_parity;
    const int wid = threadIdx.x >> 5;
    const int lane = threadIdx.x & 31;
    const int tileA = blockIdx.x;
    const int tileB = blockIdx.x + NBLK;
    const size_t f0A = (size_t)tileA * FPB;
    const size_t f0B = (size_t)tileB * FPB;

    // Clear the other parity's slots (both tiles) for the NEXT launch.
    if (threadIdx.x == 0) {
        *(volatile unsigned long long*)&g_pubS1[1 - p][tileA] = 0ull;
        *(volatile unsigned long long*)&g_pubD[1 - p][tileA] = 0ull;
        *(volatile unsigned long long*)&g_pubS1[1 - p][tileB] = 0ull;
        *(volatile unsigned long long*)&g_pubD[1 - p][tileB] = 0ull;
    }

    // -------- pipeline stage 1: reduce A, publish A, reduce B, publish B ---
    reduce_tile(x, f0A, sS1[0], sQ[0], wid, lane);
    __syncthreads();
    if (wid == 0) scan_publish(tileA, p, sS1[0], lane);
    reduce_tile(x, f0B, sS1[1], sQ[1], wid, lane);
    __syncthreads();
    if (wid == 0) {
        scan_publish(tileB, p, sS1[1], lane);
        // Join for tile A: predecessors published a full reduce-phase ago.
        stats(tileA, p, lane, sS1[0], sQ[0], sMean[0], sInv[0]);
    }
    __syncthreads();

    // -------- stage 2: warp 0 resolves B's join under A's normalize --------
    if (wid == 0) stats(tileB, p, lane, sS1[1], sQ[1], sMean[1], sInv[1]);
    norm_tile(x, w, out, f0A, sMean[0], sInv[0], wid, lane);
    __syncthreads();
    norm_tile(x, w, out, f0B, sMean[1], sInv[1], wid, lane);

    // -------- epilogue: last block flips parity ----------------------------
    __syncthreads();
    if (threadIdx.x == 0) {
        __threadfence();
        unsigned int n = atomicAdd(&g_done, 1u);
        if (n == NBLK - 1) {
            g_done = 0;
            g_parity = p ^ 1;
        }
    }
}

extern "C" void kernel_launch(void* const* d_in, const int* in_sizes, int n_in,
                              void* d_out, int out_size) {
    const float* x = (const float*)d_in[0];
    const float* w = (const float*)d_in[1];
    float* out = (float*)d_out;
    fused<<<NBLK, THREADS>>>(x, w, out);
}